// round 16
// baseline (speedup 1.0000x reference)
#include <cuda_runtime.h>
#include <cuda_bf16.h>
#include <cuda_fp16.h>
#include <cstdint>

// ---------------------------------------------------------------------------
// Arch-path detection (arch-specific pass is live; tcgen05 runs there)
// ---------------------------------------------------------------------------
#if defined(__CUDA_ARCH_SPECIFIC__) || defined(__CUDA_ARCH_FAMILY_SPECIFIC__)
#define TCG_OK 1
#else
#define TCG_OK 0
#endif

#define T_DIM 8192
#define I_DIM 4096
#define O_DIM 4096

// Static scratch: fp16 x and fp16 dequantized W (single-pass precision plan)
__device__ __half g_Ah[(size_t)T_DIM * I_DIM];
__device__ __half g_Bh[(size_t)O_DIM * I_DIM];

// ---------------------------------------------------------------------------
// Portable helpers
// ---------------------------------------------------------------------------
__device__ __forceinline__ uint32_t smem_to_u32(const void* p) {
    uint32_t a;
    asm("{ .reg .u64 t; cvta.to.shared.u64 t, %1; cvt.u32.u64 %0, t; }" : "=r"(a) : "l"(p));
    return a;
}
__device__ __forceinline__ void cp_async16(uint32_t s, const void* g) {
    asm volatile("cp.async.cg.shared.global [%0], [%1], 16;" :: "r"(s), "l"(g) : "memory");
}
#define CP_COMMIT() asm volatile("cp.async.commit_group;" ::: "memory")
#define CP_WAIT_GROUP_3() asm volatile("cp.async.wait_group 3;" ::: "memory")
#define SMEM_SWIZZLE_128B(b) ((b) ^ (((b) >> 3) & 0x70))

__device__ __forceinline__ void ldsm_x4(uint32_t* r, uint32_t addr) {
    asm volatile("ldmatrix.sync.aligned.m8n8.x4.shared.b16 {%0,%1,%2,%3}, [%4];"
                 : "=r"(r[0]), "=r"(r[1]), "=r"(r[2]), "=r"(r[3]) : "r"(addr));
}
__device__ __forceinline__ void mma16816_f16(float* d, const uint32_t* a, const uint32_t* b) {
    asm volatile(
        "mma.sync.aligned.m16n8k16.row.col.f32.f16.f16.f32 "
        "{%0,%1,%2,%3}, {%4,%5,%6,%7}, {%8,%9}, {%0,%1,%2,%3};"
        : "+f"(d[0]), "+f"(d[1]), "+f"(d[2]), "+f"(d[3])
        : "r"(a[0]), "r"(a[1]), "r"(a[2]), "r"(a[3]), "r"(b[0]), "r"(b[1]));
}

// ---------------------------------------------------------------------------
// Exact NVFP4 quantization math (bit-identical to fp32 reference)
// ---------------------------------------------------------------------------
__device__ __forceinline__ float q_e4m3(float x) {
    float s = (x > 0.f) ? 1.f : ((x < 0.f) ? -1.f : 0.f);
    float ax = fminf(fabsf(x), 448.0f);
    int e = -6;
    if (ax > 0.f) { e = ilogbf(ax); if (e < -6) e = -6; if (e > 8) e = 8; }
    float step  = __int_as_float((e + 127) << 23);
    float rstep = __int_as_float((127 - e) << 23);
    return s * (rintf(ax * rstep * 8.0f) * 0.125f * step);
}
__device__ __forceinline__ float q_e2m1(float x) {
    float s = (x > 0.f) ? 1.f : ((x < 0.f) ? -1.f : 0.f);
    float ax = fminf(fabsf(x), 6.0f);
    int e = 0;
    if (ax > 0.f) { e = ilogbf(ax); if (e < 0) e = 0; if (e > 2) e = 2; }
    float step  = __int_as_float((e + 127) << 23);
    float rstep = __int_as_float((127 - e) << 23);
    return s * (rintf(ax * rstep * 2.0f) * 0.5f * step);
}

// ---------------------------------------------------------------------------
// Fused prep kernel. Items [0, W_QUADS): dequantize 4 W elts (reciprocal-mul,
// one div per quad). Items [W_QUADS, +X_OCTS): convert 8 x elts -> fp16
// (two float4 loads, one 16B store).
// ---------------------------------------------------------------------------
constexpr size_t W_QUADS = (size_t)O_DIM * I_DIM / 4;   // 4M
constexpr size_t X_OCTS  = (size_t)T_DIM * I_DIM / 8;   // 4M
constexpr size_t PREP_ITEMS = W_QUADS + X_OCTS;         // 8M

__global__ void prep_kernel(const float* __restrict__ x,
                            const float* __restrict__ w,
                            const float* __restrict__ pba,
                            const float* __restrict__ gam) {
    size_t q = (size_t)blockIdx.x * blockDim.x + threadIdx.x;
    if (q >= PREP_ITEMS) return;
    if (q < W_QUADS) {
        size_t idx = q * 4;
        size_t o = idx >> 12;
        int i = (int)(idx & (I_DIM - 1));

        float gscale = __fdiv_rn(__ldg(gam), 2688.0f);           // /(6*448)
        float bf     = __fdiv_rn(__ldg(pba + o * (I_DIM / 16) + (i >> 4)), 6.0f);
        float bs     = q_e4m3(__fdiv_rn(bf, gscale)) * gscale;

        float rbs = (bs > 0.0f) ? __fdiv_rn(1.0f, fmaxf(bs, 1e-30f)) : 0.0f;

        float4 wv = *reinterpret_cast<const float4*>(w + idx);
        float win[4] = {wv.x, wv.y, wv.z, wv.w};
        uint32_t hp[2];
#pragma unroll
        for (int j = 0; j < 2; j++) {
            float wd0 = 0.f, wd1 = 0.f;
            if (bs > 0.0f) {
                wd0 = q_e2m1(win[2 * j + 0] * rbs) * bs;
                wd1 = q_e2m1(win[2 * j + 1] * rbs) * bs;
            }
            __half2 hh;
            hh.x = __float2half_rn(wd0);
            hh.y = __float2half_rn(wd1);
            hp[j] = *reinterpret_cast<uint32_t*>(&hh);
        }
        *reinterpret_cast<uint2*>(g_Bh + idx) = make_uint2(hp[0], hp[1]);
    } else {
        size_t idx = (q - W_QUADS) * 8;
        float4 v0 = *reinterpret_cast<const float4*>(x + idx);
        float4 v1 = *reinterpret_cast<const float4*>(x + idx + 4);
        __half2 h0, h1, h2, h3;
        h0.x = __float2half_rn(v0.x); h0.y = __float2half_rn(v0.y);
        h1.x = __float2half_rn(v0.z); h1.y = __float2half_rn(v0.w);
        h2.x = __float2half_rn(v1.x); h2.y = __float2half_rn(v1.y);
        h3.x = __float2half_rn(v1.z); h3.y = __float2half_rn(v1.w);
        uint4 pk;
        pk.x = *reinterpret_cast<uint32_t*>(&h0);
        pk.y = *reinterpret_cast<uint32_t*>(&h1);
        pk.z = *reinterpret_cast<uint32_t*>(&h2);
        pk.w = *reinterpret_cast<uint32_t*>(&h3);
        *reinterpret_cast<uint4*>(g_Ah + idx) = pk;
    }
}

// ===========================================================================
// PATH A: cta_group::2 tcgen05 GEMM on the PROVEN warp-specialized engine.
// 2-CTA cluster computes M=256 x N=256; each CTA ingests A 16KB + B(N/2) 16KB
// per BK=64 chunk (32KB, was 48KB). Producers free-run 4 stages ahead;
// rank1 warp-8 relays full -> rank0 pair barrier; rank0 warp-8 issues cg2 MMA
// and commit-multicasts done to both CTAs. No __syncthreads in mainloop.
// ===========================================================================
constexpr int BK = 64;
constexpr int NCH = I_DIM / BK;                // 64 chunks
constexpr int NSTG = 4;
constexpr int A_BYTES = 128 * 128;             // 16 KB (local 128 M-rows)
constexpr int STG_BYTES = 2 * A_BYTES;         // 32 KB (A + local B half)
constexpr int SM_TMEMPTR = 0;
constexpr int SM_FULLL = 16;                   // 4 x 8B, count=256 (local cp.async)
constexpr int SM_PAIR  = 48;                   // 4 x 8B, count=1 (rank1 relay, on rank0)
constexpr int SM_DONE  = 80;                   // 4 x 8B, count=1 (commit multicast)
constexpr int SM_TILES = 1024;
constexpr int SMEM_DYN = SM_TILES + NSTG * STG_BYTES;   // 132096 B
constexpr int GEMM_THREADS = 288;              // 256 producers + warp 8

// idesc: D=F32, A=F16, B=F16, N=256, M_TOTAL=256 (cg2)
constexpr uint32_t IDESC2 =
    (1u << 4) | ((256 / 8) << 17) | ((256 / 16) << 24);

static constexpr uint64_t SMEM_DESC_BASE_SW128 =
    (uint64_t(2) << 61) | (uint64_t(1) << 46) | (uint64_t(64) << 32) | (uint64_t(1) << 16);
#define MAKE_SMEM_DESC(base_addr) \
    (SMEM_DESC_BASE_SW128 | ((uint64_t)((base_addr) >> 4) & 0x3FFF))

#if TCG_OK
__device__ __forceinline__ uint32_t elect_one_pred() {
    uint32_t pred;
    asm volatile(
        "{\n\t.reg .pred p;\n\telect.sync _|p, 0xFFFFFFFF;\n\tselp.b32 %0, 1, 0, p;\n\t}"
        : "=r"(pred));
    return pred;
}
__device__ __forceinline__ uint32_t cluster_ctarank() {
    uint32_t r; asm("mov.u32 %0, %%cluster_ctarank;" : "=r"(r)); return r;
}

#define MBARRIER_INIT(addr, count) \
    asm volatile("mbarrier.init.shared.b64 [%0], %1;" :: "r"((uint32_t)(addr)), "r"((uint32_t)(count)) : "memory")

// cta-scope acquire wait (local producer/consumer edges)
#define MBARRIER_WAIT_PARITY(mbar_smem_addr, phase_parity) do { \
    uint32_t _mbar = (uint32_t)(mbar_smem_addr); \
    uint32_t _parity = (uint32_t)(phase_parity); \
    uint32_t _done; \
    asm volatile( \
        "{\n\t.reg .pred p;\n\t" \
        "mbarrier.try_wait.parity.acquire.cta.shared::cta.b64 p, [%1], %2;\n\t" \
        "selp.b32 %0, 1, 0, p;\n\t}" \
        : "=r"(_done) : "r"(_mbar), "r"(_parity) : "memory"); \
    if (!_done) { \
        asm volatile( \
            "{\n\t.reg .pred P1;\n\t" \
            "WAIT_LOOP_%=:\n\t" \
            "mbarrier.try_wait.parity.acquire.cta.shared::cta.b64 P1, [%0], %1, 0x989680;\n\t" \
            "@P1 bra.uni WAIT_DONE_%=;\n\t" \
            "bra.uni WAIT_LOOP_%=;\n\t" \
            "WAIT_DONE_%=:\n\t}" \
            :: "r"(_mbar), "r"(_parity) : "memory"); \
    } \
} while(0)

// cluster-scope acquire wait (cross-CTA arrivals: relay, commit multicast)
#define MBAR_WAIT_CL(mbar_smem_addr, phase_parity) do { \
    uint32_t _mbar = (uint32_t)(mbar_smem_addr); \
    uint32_t _parity = (uint32_t)(phase_parity); \
    uint32_t _done; \
    asm volatile( \
        "{\n\t.reg .pred p;\n\t" \
        "mbarrier.try_wait.parity.acquire.cluster.shared::cta.b64 p, [%1], %2;\n\t" \
        "selp.b32 %0, 1, 0, p;\n\t}" \
        : "=r"(_done) : "r"(_mbar), "r"(_parity) : "memory"); \
    if (!_done) { \
        asm volatile( \
            "{\n\t.reg .pred P1;\n\t" \
            "WAIT_LOOP_%=:\n\t" \
            "mbarrier.try_wait.parity.acquire.cluster.shared::cta.b64 P1, [%0], %1, 0x989680;\n\t" \
            "@P1 bra.uni WAIT_DONE_%=;\n\t" \
            "bra.uni WAIT_LOOP_%=;\n\t" \
            "WAIT_DONE_%=:\n\t}" \
            :: "r"(_mbar), "r"(_parity) : "memory"); \
    } \
} while(0)

// Arrive when all prior cp.async of THIS thread complete (.noinc, count pre-set)
#define CP_ASYNC_MBAR_ARRIVE(addr) \
    asm volatile("cp.async.mbarrier.arrive.noinc.shared::cta.b64 [%0];" \
        :: "r"((uint32_t)(addr)) : "memory")

// Arrive on same smem-offset mbarrier in cluster CTA 0
#define MBARRIER_ARRIVE_RANK0(local_addr) \
    asm volatile( \
        "{\n\t.reg .b32 r;\n\t" \
        "mapa.shared::cluster.u32 r, %0, %1;\n\t" \
        "mbarrier.arrive.shared::cluster.b64 _, [r];\n\t}" \
        :: "r"((uint32_t)(local_addr)), "r"(0u) : "memory")

#define TCGEN05_ALLOC_CG2(smem_result_addr, nCols) \
    asm volatile("tcgen05.alloc.cta_group::2.sync.aligned.shared::cta.b32 [%0], %1;" \
        :: "r"((uint32_t)(smem_result_addr)), "r"((uint32_t)(nCols)) : "memory")
#define TCGEN05_DEALLOC_CG2(tmem_addr, nCols) \
    asm volatile("tcgen05.dealloc.cta_group::2.sync.aligned.b32 %0, %1;" \
        :: "r"(tmem_addr), "r"((uint32_t)(nCols)))
#define TCGEN05_RELINQUISH_CG2() \
    asm volatile("tcgen05.relinquish_alloc_permit.cta_group::2.sync.aligned;")
#define TCGEN05_COMMIT_MC_CG2(mbar, mask) \
    asm volatile("tcgen05.commit.cta_group::2.mbarrier::arrive::one.shared::cluster.multicast::cluster.b64 [%0], %1;" \
        :: "r"((uint32_t)(mbar)), "h"((uint16_t)(mask)) : "memory")
#define TCGEN05_WAIT_LD() asm volatile("tcgen05.wait::ld.sync.aligned;" ::: "memory")
#define TCGEN05_FENCE_AFTER() asm volatile("tcgen05.fence::after_thread_sync;" ::: "memory")
#define FENCE_PROXY_ASYNC() asm volatile("fence.proxy.async;" ::: "memory")
#define FENCE_PROXY_ASYNC_SHARED_CTA() asm volatile("fence.proxy.async.shared::cta;" ::: "memory")
#define CLUSTER_SYNC() do { \
    asm volatile("barrier.cluster.arrive.aligned;" ::: "memory"); \
    asm volatile("barrier.cluster.wait.aligned;" ::: "memory"); \
} while (0)

#define TCGEN05_LD_32X32B_X32(r, tmem_addr) \
    asm volatile( \
        "tcgen05.ld.sync.aligned.32x32b.x32.b32 " \
        "{%0, %1, %2, %3, %4, %5, %6, %7, " \
        " %8, %9, %10, %11, %12, %13, %14, %15, " \
        " %16, %17, %18, %19, %20, %21, %22, %23, " \
        " %24, %25, %26, %27, %28, %29, %30, %31}, [%32];" \
        : "=r"((r)[0]),  "=r"((r)[1]),  "=r"((r)[2]),  "=r"((r)[3]), \
          "=r"((r)[4]),  "=r"((r)[5]),  "=r"((r)[6]),  "=r"((r)[7]), \
          "=r"((r)[8]),  "=r"((r)[9]),  "=r"((r)[10]), "=r"((r)[11]), \
          "=r"((r)[12]), "=r"((r)[13]), "=r"((r)[14]), "=r"((r)[15]), \
          "=r"((r)[16]), "=r"((r)[17]), "=r"((r)[18]), "=r"((r)[19]), \
          "=r"((r)[20]), "=r"((r)[21]), "=r"((r)[22]), "=r"((r)[23]), \
          "=r"((r)[24]), "=r"((r)[25]), "=r"((r)[26]), "=r"((r)[27]), \
          "=r"((r)[28]), "=r"((r)[29]), "=r"((r)[30]), "=r"((r)[31]) \
        : "r"(tmem_addr))

__device__ __forceinline__ void mma_f16_ss_cg2(uint32_t d, uint64_t ad, uint64_t bd,
                                               uint32_t idesc, bool acc) {
    uint32_t en = acc ? 1u : 0u;
    asm volatile(
        "{\n\t.reg .pred p;\n\tsetp.ne.u32 p, %5, 0;\n\t"
        "tcgen05.mma.cta_group::2.kind::f16 [%0], %1, %2, %3, "
        "{%4, %4, %4, %4, %4, %4, %4, %4}, p;\n\t}"
        :: "r"(d), "l"(ad), "l"(bd), "r"(idesc), "r"(0u), "r"(en)
        : "memory");
}
#endif  // TCG_OK

__global__ void __launch_bounds__(GEMM_THREADS, 1) __cluster_dims__(2, 1, 1)
nvfp4_gemm_tcg2(float* __restrict__ out) {
#if TCG_OK
    extern __shared__ char smem[];
    const uint32_t sb = smem_to_u32(smem);
    const int tid = (int)threadIdx.x;
    const int wid = tid >> 5;
    const int lid = tid & 31;
    const uint32_t rank = cluster_ctarank();

    if (wid == 0) TCGEN05_ALLOC_CG2(sb + SM_TMEMPTR, 256);
    if (tid == 0) {
#pragma unroll
        for (int s = 0; s < NSTG; s++) {
            MBARRIER_INIT(sb + SM_FULLL + 8 * s, 256);  // local cp.async arrivals
            MBARRIER_INIT(sb + SM_PAIR  + 8 * s, 1);    // rank1 relay (used on rank0)
            MBARRIER_INIT(sb + SM_DONE  + 8 * s, 1);    // commit multicast
        }
    }
    __syncthreads();
    CLUSTER_SYNC();   // peer barriers initialized before cross-CTA arrivals

    uint32_t tmem;
    asm volatile("ld.shared.b32 %0, [%1];" : "=r"(tmem) : "r"(sb + SM_TMEMPTR));

    const size_t n0 = (size_t)(blockIdx.x >> 1) * 256;
    const size_t m0 = (size_t)blockIdx.y * 256;

    // ---------------- producers: tids 0..255, 4 A + 4 B slots of 16B ----------
    if (tid < 256) {
        uint32_t a_soff[4], b_soff[4];
        size_t a_goff[4], b_goff[4];
#pragma unroll
        for (int i = 0; i < 4; i++) {
            int idx = tid + i * 256;
            int r = idx >> 3, c16 = idx & 7;
            uint32_t sw = SMEM_SWIZZLE_128B((uint32_t)(r * 128 + c16 * 16));
            a_soff[i] = sw;
            b_soff[i] = (uint32_t)A_BYTES + sw;
            a_goff[i] = (m0 + rank * 128 + r) * (size_t)I_DIM + (size_t)c16 * 8;
            b_goff[i] = (n0 + rank * 128 + r) * (size_t)I_DIM + (size_t)c16 * 8;
        }
#pragma unroll 1
        for (int c = 0; c < NCH; c++) {
            int s = c & (NSTG - 1);
            if (c >= NSTG)                                 // stage reuse gate
                MBAR_WAIT_CL(sb + SM_DONE + 8 * s, ((c >> 2) - 1) & 1);
            uint32_t base = sb + SM_TILES + s * STG_BYTES;
            size_t kk = (size_t)c * BK;
#pragma unroll
            for (int i = 0; i < 4; i++) cp_async16(base + a_soff[i], g_Ah + a_goff[i] + kk);
#pragma unroll
            for (int i = 0; i < 4; i++) cp_async16(base + b_soff[i], g_Bh + b_goff[i] + kk);
            CP_ASYNC_MBAR_ARRIVE(sb + SM_FULLL + 8 * s);
        }
    }

    // ---------------- warp 8: rank0 = MMA issuer, rank1 = relay --------------
    if (wid == 8) {
        if (elect_one_pred()) {
            if (rank == 0) {
#pragma unroll 1
                for (int k = 0; k < NCH; k++) {
                    int s = k & (NSTG - 1);
                    int par = (k >> 2) & 1;
                    MBARRIER_WAIT_PARITY(sb + SM_FULLL + 8 * s, par);  // own tiles
                    MBAR_WAIT_CL(sb + SM_PAIR + 8 * s, par);           // peer tiles
                    FENCE_PROXY_ASYNC_SHARED_CTA();
                    uint32_t base = sb + SM_TILES + s * STG_BYTES;
                    uint64_t ad = MAKE_SMEM_DESC(base);
                    uint64_t bd = MAKE_SMEM_DESC(base + A_BYTES);
                    bool first = (k == 0);
#pragma unroll
                    for (int j = 0; j < 4; j++)   // 4 x K=16 cover BK=64 (+2 = 32B)
                        mma_f16_ss_cg2(tmem, ad + j * 2, bd + j * 2, IDESC2,
                                       !(first && j == 0));
                    TCGEN05_COMMIT_MC_CG2(sb + SM_DONE + 8 * s, 0x3);
                }
            } else {
#pragma unroll 1
                for (int k = 0; k < NCH; k++) {
                    int s = k & (NSTG - 1);
                    MBARRIER_WAIT_PARITY(sb + SM_FULLL + 8 * s, (k >> 2) & 1);
                    FENCE_PROXY_ASYNC();   // make local fills visible cluster-wide
                    MBARRIER_ARRIVE_RANK0(sb + SM_PAIR + 8 * s);
                }
            }
        }
    }

    // ---------------- epilogue: wait final commit, drain local TMEM ----------
    MBAR_WAIT_CL(sb + SM_DONE + 8 * ((NCH - 1) & (NSTG - 1)),
                 ((NCH - 1) >> 2) & 1);
    TCGEN05_FENCE_AFTER();

    // local TMEM holds this CTA's 128 M-rows x 256 N-cols (fp32)
    if (wid < 4) {
        size_t row = m0 + rank * 128 + (size_t)(wid * 32 + lid);
        float* op = out + row * (size_t)O_DIM + n0;
#pragma unroll 1
        for (int cb = 0; cb < 8; cb++) {
            uint32_t r[32];
            TCGEN05_LD_32X32B_X32(r, tmem + cb * 32);
            TCGEN05_WAIT_LD();
#pragma unroll
            for (int q = 0; q < 8; q++) {
                float4 v;
                v.x = __uint_as_float(r[q * 4 + 0]);
                v.y = __uint_as_float(r[q * 4 + 1]);
                v.z = __uint_as_float(r[q * 4 + 2]);
                v.w = __uint_as_float(r[q * 4 + 3]);
                *reinterpret_cast<float4*>(op + cb * 32 + q * 4) = v;
            }
        }
    }

    __syncthreads();
    if (wid == 0) {
        TCGEN05_RELINQUISH_CG2();
        TCGEN05_DEALLOC_CG2(tmem, 256);
    }
    CLUSTER_SYNC();   // neither CTA exits while peer may still touch its SMEM
#endif  // TCG_OK
}

// ===========================================================================
// PATH B: portable mma.sync fallback (fp16) — empty body in the live cubin;
// launched only if the runtime-loaded tcgen05 kernel is the empty variant.
// ===========================================================================
constexpr int FBM = 128, FBN = 128, FBK = 64;
constexpr int FNCH = I_DIM / FBK;
constexpr int FSTG = 4;
constexpr int F_ABYTES = FBM * 128;
constexpr int F_STGB = F_ABYTES + FBN * 128;
constexpr int F_SMEM = FSTG * F_STGB;

__global__ void __launch_bounds__(256, 1)
nvfp4_gemm_mmasync(float* __restrict__ out) {
#if !TCG_OK
    extern __shared__ char smem[];
    const uint32_t sb = smem_to_u32(smem);
    const int tid = (int)threadIdx.x;
    const int wid = tid >> 5;
    const int lane = tid & 31;
    const int wm = wid & 1;
    const int wn = wid >> 1;

    const size_t m0 = (size_t)blockIdx.y * FBM;
    const size_t n0 = (size_t)blockIdx.x * FBN;

    uint32_t soff[8];
    size_t goff[8];
#pragma unroll
    for (int i = 0; i < 8; i++) {
        int idx = tid + i * 256;
        if (i < 4) {
            int r = idx >> 3, c16 = idx & 7;
            soff[i] = SMEM_SWIZZLE_128B((uint32_t)(r * 128 + c16 * 16));
            goff[i] = (m0 + r) * (size_t)I_DIM + (size_t)c16 * 8;
        } else {
            int idx2 = idx - 1024;
            int r = idx2 >> 3, c16 = idx2 & 7;
            soff[i] = (uint32_t)F_ABYTES + SMEM_SWIZZLE_128B((uint32_t)(r * 128 + c16 * 16));
            goff[i] = (n0 + r) * (size_t)I_DIM + (size_t)c16 * 8;
        }
    }

    auto load_chunk = [&](int c) {
        int s = c & (FSTG - 1);
        uint32_t base = sb + s * F_STGB;
        size_t kk = (size_t)c * FBK;
#pragma unroll
        for (int i = 0; i < 4; i++) cp_async16(base + soff[i], g_Ah + goff[i] + kk);
#pragma unroll
        for (int i = 4; i < 8; i++) cp_async16(base + soff[i], g_Bh + goff[i] + kk);
    };

    uint32_t arow128[4], axor[4];
    const uint32_t ahix = (uint32_t)((lane >> 4) * 16);
#pragma unroll
    for (int i = 0; i < 4; i++) {
        int row = wm * 64 + i * 16 + (lane & 7) + ((lane >> 3) & 1) * 8;
        arow128[i] = (uint32_t)(row * 128);
        axor[i] = (uint32_t)((row & 7) << 4);
    }
    uint32_t brow128[2], bxor[2];
    const uint32_t bhix = (uint32_t)(((lane >> 3) & 1) * 16);
#pragma unroll
    for (int jj = 0; jj < 2; jj++) {
        int row = wn * 32 + jj * 16 + (lane & 7) + ((lane >> 4) & 1) * 8;
        brow128[jj] = (uint32_t)(row * 128);
        bxor[jj] = (uint32_t)((row & 7) << 4);
    }

    float c[4][4][4];
#pragma unroll
    for (int i = 0; i < 4; i++)
#pragma unroll
        for (int j = 0; j < 4; j++)
#pragma unroll
            for (int r = 0; r < 4; r++) c[i][j][r] = 0.0f;

#pragma unroll 1
    for (int cch = 0; cch < FSTG; cch++) { load_chunk(cch); CP_COMMIT(); }

#pragma unroll 1
    for (int k = 0; k < FNCH; k++) {
        CP_WAIT_GROUP_3();
        __syncthreads();
        uint32_t Abase = sb + (uint32_t)((k & (FSTG - 1)) * F_STGB);
        uint32_t Bbase = Abase + F_ABYTES;
#pragma unroll
        for (int q = 0; q < 4; q++) {
            uint32_t qa = (uint32_t)(q * 32) + ahix;
            uint32_t qb = (uint32_t)(q * 32) + bhix;
            uint32_t a[4][4], b[2][4];
#pragma unroll
            for (int i = 0; i < 4; i++)
                ldsm_x4(a[i], Abase + arow128[i] + (qa ^ axor[i]));
#pragma unroll
            for (int jj = 0; jj < 2; jj++)
                ldsm_x4(b[jj], Bbase + brow128[jj] + (qb ^ bxor[jj]));
#pragma unroll
            for (int i = 0; i < 4; i++)
#pragma unroll
                for (int jj = 0; jj < 2; jj++) {
                    mma16816_f16(c[i][2 * jj + 0], a[i], &b[jj][0]);
                    mma16816_f16(c[i][2 * jj + 1], a[i], &b[jj][2]);
                }
        }
        __syncthreads();
        if (k + FSTG < FNCH) load_chunk(k + FSTG);
        CP_COMMIT();
    }

    const size_t rbase = m0 + (size_t)(wm * 64) + (size_t)(lane >> 2);
    const size_t cbase = n0 + (size_t)(wn * 32) + (size_t)((lane & 3) * 2);
#pragma unroll
    for (int i = 0; i < 4; i++)
#pragma unroll
        for (int j = 0; j < 4; j++) {
            size_t row = rbase + (size_t)(i * 16);
            size_t col = cbase + (size_t)(j * 8);
            *reinterpret_cast<float2*>(out + row * O_DIM + col) =
                make_float2(c[i][j][0], c[i][j][1]);
            *reinterpret_cast<float2*>(out + (row + 8) * O_DIM + col) =
                make_float2(c[i][j][2], c[i][j][3]);
        }
#endif  // !TCG_OK
}

// ---------------------------------------------------------------------------
// Launch
// ---------------------------------------------------------------------------
extern "C" void kernel_launch(void* const* d_in, const int* in_sizes, int n_in,
                              void* d_out, int out_size) {
    const float* x   = (const float*)d_in[0];
    const float* w   = (const float*)d_in[1];
    const float* pba = (const float*)d_in[2];
    const float* gam = (const float*)d_in[3];
    float* out = (float*)d_out;

    cudaFuncSetAttribute(nvfp4_gemm_tcg2,
                         cudaFuncAttributeMaxDynamicSharedMemorySize, SMEM_DYN);
    cudaFuncSetAttribute(nvfp4_gemm_mmasync,
                         cudaFuncAttributeMaxDynamicSharedMemorySize, F_SMEM);

    // Which cubin did the runtime load? Real tcgen05 kernel uses many regs;
    // the empty-body variant (non-arch-specific pass) uses ~16.
    cudaFuncAttributes attr{};
    cudaFuncGetAttributes(&attr, nvfp4_gemm_tcg2);
    const bool tcg_live = (attr.numRegs >= 32);

    {
        prep_kernel<<<(unsigned)((PREP_ITEMS + 255) / 256), 256>>>(x, w, pba, gam);
    }
    {
        dim3 grid(2 * (O_DIM / 256), T_DIM / 256, 1);   // (32, 32) = 1024 CTAs
        nvfp4_gemm_tcg2<<<grid, GEMM_THREADS, SMEM_DYN>>>(out);
    }
    if (!tcg_live) {
        dim3 grid(O_DIM / FBN, T_DIM / FBM, 1);         // insurance path
        nvfp4_gemm_mmasync<<<grid, 256, F_SMEM>>>(out);
    }
}

// round 17
// speedup vs baseline: 1.4896x; 1.4896x over previous
#include <cuda_runtime.h>
#include <cuda_bf16.h>
#include <cuda_fp16.h>
#include <cstdint>

// ---------------------------------------------------------------------------
// Arch-path detection (arch-specific pass is live; tcgen05 runs there)
// ---------------------------------------------------------------------------
#if defined(__CUDA_ARCH_SPECIFIC__) || defined(__CUDA_ARCH_FAMILY_SPECIFIC__)
#define TCG_OK 1
#else
#define TCG_OK 0
#endif

#define T_DIM 8192
#define I_DIM 4096
#define O_DIM 4096

// Static scratch: fp16 x and fp16 dequantized W (single-pass precision plan)
__device__ __half g_Ah[(size_t)T_DIM * I_DIM];
__device__ __half g_Bh[(size_t)O_DIM * I_DIM];

// ---------------------------------------------------------------------------
// Portable helpers
// ---------------------------------------------------------------------------
__device__ __forceinline__ uint32_t smem_to_u32(const void* p) {
    uint32_t a;
    asm("{ .reg .u64 t; cvta.to.shared.u64 t, %1; cvt.u32.u64 %0, t; }" : "=r"(a) : "l"(p));
    return a;
}
__device__ __forceinline__ void cp_async16(uint32_t s, const void* g) {
    asm volatile("cp.async.cg.shared.global [%0], [%1], 16;" :: "r"(s), "l"(g) : "memory");
}
#define CP_COMMIT() asm volatile("cp.async.commit_group;" ::: "memory")
#define CP_WAIT_GROUP_3() asm volatile("cp.async.wait_group 3;" ::: "memory")
#define SMEM_SWIZZLE_128B(b) ((b) ^ (((b) >> 3) & 0x70))

__device__ __forceinline__ void ldsm_x4(uint32_t* r, uint32_t addr) {
    asm volatile("ldmatrix.sync.aligned.m8n8.x4.shared.b16 {%0,%1,%2,%3}, [%4];"
                 : "=r"(r[0]), "=r"(r[1]), "=r"(r[2]), "=r"(r[3]) : "r"(addr));
}
__device__ __forceinline__ void mma16816_f16(float* d, const uint32_t* a, const uint32_t* b) {
    asm volatile(
        "mma.sync.aligned.m16n8k16.row.col.f32.f16.f16.f32 "
        "{%0,%1,%2,%3}, {%4,%5,%6,%7}, {%8,%9}, {%0,%1,%2,%3};"
        : "+f"(d[0]), "+f"(d[1]), "+f"(d[2]), "+f"(d[3])
        : "r"(a[0]), "r"(a[1]), "r"(a[2]), "r"(a[3]), "r"(b[0]), "r"(b[1]));
}

// ---------------------------------------------------------------------------
// Exact NVFP4 quantization math (bit-identical to fp32 reference)
// ---------------------------------------------------------------------------
__device__ __forceinline__ float q_e4m3(float x) {
    float s = (x > 0.f) ? 1.f : ((x < 0.f) ? -1.f : 0.f);
    float ax = fminf(fabsf(x), 448.0f);
    int e = -6;
    if (ax > 0.f) { e = ilogbf(ax); if (e < -6) e = -6; if (e > 8) e = 8; }
    float step  = __int_as_float((e + 127) << 23);
    float rstep = __int_as_float((127 - e) << 23);
    return s * (rintf(ax * rstep * 8.0f) * 0.125f * step);
}
__device__ __forceinline__ float q_e2m1(float x) {
    float s = (x > 0.f) ? 1.f : ((x < 0.f) ? -1.f : 0.f);
    float ax = fminf(fabsf(x), 6.0f);
    int e = 0;
    if (ax > 0.f) { e = ilogbf(ax); if (e < 0) e = 0; if (e > 2) e = 2; }
    float step  = __int_as_float((e + 127) << 23);
    float rstep = __int_as_float((127 - e) << 23);
    return s * (rintf(ax * rstep * 2.0f) * 0.5f * step);
}

// ---------------------------------------------------------------------------
// Fused prep kernel, both paths x8.
// Items [0, W_OCTS): dequantize 8 W elts — one 16-block scale + ONE divide
// serves all 8 (an 8-aligned octet never crosses a 16-block boundary).
// Items [W_OCTS, +X_OCTS): convert 8 x elts -> fp16.
// ---------------------------------------------------------------------------
constexpr size_t W_OCTS = (size_t)O_DIM * I_DIM / 8;    // 2M
constexpr size_t X_OCTS = (size_t)T_DIM * I_DIM / 8;    // 4M
constexpr size_t PREP_ITEMS = W_OCTS + X_OCTS;          // 6M

__global__ void prep_kernel(const float* __restrict__ x,
                            const float* __restrict__ w,
                            const float* __restrict__ pba,
                            const float* __restrict__ gam) {
    size_t q = (size_t)blockIdx.x * blockDim.x + threadIdx.x;
    if (q >= PREP_ITEMS) return;
    if (q < W_OCTS) {
        size_t idx = q * 8;
        size_t o = idx >> 12;
        int i = (int)(idx & (I_DIM - 1));

        float gscale = __fdiv_rn(__ldg(gam), 2688.0f);           // /(6*448)
        float bf     = __fdiv_rn(__ldg(pba + o * (I_DIM / 16) + (i >> 4)), 6.0f);
        float bs     = q_e4m3(__fdiv_rn(bf, gscale)) * gscale;
        float rbs    = (bs > 0.0f) ? __fdiv_rn(1.0f, fmaxf(bs, 1e-30f)) : 0.0f;

        float4 wv0 = *reinterpret_cast<const float4*>(w + idx);
        float4 wv1 = *reinterpret_cast<const float4*>(w + idx + 4);
        float win[8] = {wv0.x, wv0.y, wv0.z, wv0.w, wv1.x, wv1.y, wv1.z, wv1.w};
        uint32_t hp[4];
#pragma unroll
        for (int j = 0; j < 4; j++) {
            float wd0 = 0.f, wd1 = 0.f;
            if (bs > 0.0f) {
                wd0 = q_e2m1(win[2 * j + 0] * rbs) * bs;
                wd1 = q_e2m1(win[2 * j + 1] * rbs) * bs;
            }
            __half2 hh;
            hh.x = __float2half_rn(wd0);
            hh.y = __float2half_rn(wd1);
            hp[j] = *reinterpret_cast<uint32_t*>(&hh);
        }
        uint4 pk = make_uint4(hp[0], hp[1], hp[2], hp[3]);
        *reinterpret_cast<uint4*>(g_Bh + idx) = pk;
    } else {
        size_t idx = (q - W_OCTS) * 8;
        float4 v0 = *reinterpret_cast<const float4*>(x + idx);
        float4 v1 = *reinterpret_cast<const float4*>(x + idx + 4);
        __half2 h0, h1, h2, h3;
        h0.x = __float2half_rn(v0.x); h0.y = __float2half_rn(v0.y);
        h1.x = __float2half_rn(v0.z); h1.y = __float2half_rn(v0.w);
        h2.x = __float2half_rn(v1.x); h2.y = __float2half_rn(v1.y);
        h3.x = __float2half_rn(v1.z); h3.y = __float2half_rn(v1.w);
        uint4 pk;
        pk.x = *reinterpret_cast<uint32_t*>(&h0);
        pk.y = *reinterpret_cast<uint32_t*>(&h1);
        pk.z = *reinterpret_cast<uint32_t*>(&h2);
        pk.w = *reinterpret_cast<uint32_t*>(&h3);
        *reinterpret_cast<uint4*>(g_Ah + idx) = pk;
    }
}

// ===========================================================================
// PATH A: cg1 tcgen05 GEMM — EXACT R14 winner (272.8us run): BM=128 x BN=256,
// BK=64, 4 stages, warp-specialized 256 producers + MMA warp, cp.async-mbarrier
// ring, no __syncthreads / wait_group in the mainloop.
// ===========================================================================
constexpr int BM = 128;
constexpr int BN = 256;
constexpr int BK = 64;
constexpr int NCH = I_DIM / BK;                // 64 chunks
constexpr int NSTG = 4;
constexpr int A_BYTES = BM * 128;              // 16 KB
constexpr int B_BYTES = BN * 128;              // 32 KB
constexpr int STG_BYTES = A_BYTES + B_BYTES;   // 48 KB
constexpr int SM_TMEMPTR = 0;
constexpr int SM_FULL = 16;                    // 4 x 8B, count=256 (producers)
constexpr int SM_DONE = 48;                    // 4 x 8B, count=1   (commit)
constexpr int SM_TILES = 1024;
constexpr int SMEM_DYN = SM_TILES + NSTG * STG_BYTES;   // 197632 B
constexpr int GEMM_THREADS = 288;              // 256 producers + MMA warp (wid 8)

// idesc: D=F32, A=F16, B=F16, N=256, M=128
constexpr uint32_t IDESC =
    (1u << 4) | ((BN / 8) << 17) | ((BM / 16) << 24);

static constexpr uint64_t SMEM_DESC_BASE_SW128 =
    (uint64_t(2) << 61) | (uint64_t(1) << 46) | (uint64_t(64) << 32) | (uint64_t(1) << 16);
#define MAKE_SMEM_DESC(base_addr) \
    (SMEM_DESC_BASE_SW128 | ((uint64_t)((base_addr) >> 4) & 0x3FFF))

#if TCG_OK
__device__ __forceinline__ uint32_t elect_one_pred() {
    uint32_t pred;
    asm volatile(
        "{\n\t.reg .pred p;\n\telect.sync _|p, 0xFFFFFFFF;\n\tselp.b32 %0, 1, 0, p;\n\t}"
        : "=r"(pred));
    return pred;
}

#define MBARRIER_INIT(addr, count) \
    asm volatile("mbarrier.init.shared.b64 [%0], %1;" :: "r"((uint32_t)(addr)), "r"((uint32_t)(count)) : "memory")

#define MBARRIER_WAIT_PARITY(mbar_smem_addr, phase_parity) do { \
    uint32_t _mbar = (uint32_t)(mbar_smem_addr); \
    uint32_t _parity = (uint32_t)(phase_parity); \
    uint32_t _done; \
    asm volatile( \
        "{\n\t.reg .pred p;\n\t" \
        "mbarrier.try_wait.parity.acquire.cta.shared::cta.b64 p, [%1], %2;\n\t" \
        "selp.b32 %0, 1, 0, p;\n\t}" \
        : "=r"(_done) : "r"(_mbar), "r"(_parity) : "memory"); \
    if (!_done) { \
        asm volatile( \
            "{\n\t.reg .pred P1;\n\t" \
            "WAIT_LOOP_%=:\n\t" \
            "mbarrier.try_wait.parity.acquire.cta.shared::cta.b64 P1, [%0], %1, 0x989680;\n\t" \
            "@P1 bra.uni WAIT_DONE_%=;\n\t" \
            "bra.uni WAIT_LOOP_%=;\n\t" \
            "WAIT_DONE_%=:\n\t}" \
            :: "r"(_mbar), "r"(_parity) : "memory"); \
    } \
} while(0)

// Arrive on mbarrier when all prior cp.async of THIS thread have completed.
// .noinc: expected count pre-accounted at init (count = 256 producers).
#define CP_ASYNC_MBAR_ARRIVE(addr) \
    asm volatile("cp.async.mbarrier.arrive.noinc.shared::cta.b64 [%0];" \
        :: "r"((uint32_t)(addr)) : "memory")

#define TCGEN05_ALLOC(smem_result_addr, nCols) \
    asm volatile("tcgen05.alloc.cta_group::1.sync.aligned.shared::cta.b32 [%0], %1;" \
        :: "r"((uint32_t)(smem_result_addr)), "r"((uint32_t)(nCols)) : "memory")
#define TCGEN05_DEALLOC(tmem_addr, nCols) \
    asm volatile("tcgen05.dealloc.cta_group::1.sync.aligned.b32 %0, %1;" \
        :: "r"(tmem_addr), "r"((uint32_t)(nCols)))
#define TCGEN05_RELINQUISH_ALLOC_PERMIT() \
    asm volatile("tcgen05.relinquish_alloc_permit.cta_group::1.sync.aligned;")
#define TCGEN05_COMMIT(mbar_smem_addr) \
    asm volatile("tcgen05.commit.cta_group::1.mbarrier::arrive::one.shared::cluster.b64 [%0];" \
        :: "r"((uint32_t)(mbar_smem_addr)) : "memory")
#define TCGEN05_WAIT_LD() asm volatile("tcgen05.wait::ld.sync.aligned;" ::: "memory")
#define TCGEN05_FENCE_AFTER() asm volatile("tcgen05.fence::after_thread_sync;" ::: "memory")
#define FENCE_PROXY_ASYNC_SHARED_CTA() asm volatile("fence.proxy.async.shared::cta;" ::: "memory")

#define TCGEN05_LD_32X32B_X32(r, tmem_addr) \
    asm volatile( \
        "tcgen05.ld.sync.aligned.32x32b.x32.b32 " \
        "{%0, %1, %2, %3, %4, %5, %6, %7, " \
        " %8, %9, %10, %11, %12, %13, %14, %15, " \
        " %16, %17, %18, %19, %20, %21, %22, %23, " \
        " %24, %25, %26, %27, %28, %29, %30, %31}, [%32];" \
        : "=r"((r)[0]),  "=r"((r)[1]),  "=r"((r)[2]),  "=r"((r)[3]), \
          "=r"((r)[4]),  "=r"((r)[5]),  "=r"((r)[6]),  "=r"((r)[7]), \
          "=r"((r)[8]),  "=r"((r)[9]),  "=r"((r)[10]), "=r"((r)[11]), \
          "=r"((r)[12]), "=r"((r)[13]), "=r"((r)[14]), "=r"((r)[15]), \
          "=r"((r)[16]), "=r"((r)[17]), "=r"((r)[18]), "=r"((r)[19]), \
          "=r"((r)[20]), "=r"((r)[21]), "=r"((r)[22]), "=r"((r)[23]), \
          "=r"((r)[24]), "=r"((r)[25]), "=r"((r)[26]), "=r"((r)[27]), \
          "=r"((r)[28]), "=r"((r)[29]), "=r"((r)[30]), "=r"((r)[31]) \
        : "r"(tmem_addr))

__device__ __forceinline__ void mma_f16_ss(uint32_t d, uint64_t ad, uint64_t bd,
                                           uint32_t idesc, bool acc) {
    uint32_t en = acc ? 1u : 0u;
    asm volatile(
        "{\n\t.reg .pred p;\n\tsetp.ne.u32 p, %5, 0;\n\t"
        "tcgen05.mma.cta_group::1.kind::f16 [%0], %1, %2, %3, {%4, %4, %4, %4}, p;\n\t}"
        :: "r"(d), "l"(ad), "l"(bd), "r"(idesc), "r"(0u), "r"(en)
        : "memory");
}
#endif  // TCG_OK

__global__ void __launch_bounds__(GEMM_THREADS, 1)
nvfp4_gemm_tcgen05(float* __restrict__ out) {
#if TCG_OK
    extern __shared__ char smem[];
    const uint32_t sb = smem_to_u32(smem);
    const int tid = (int)threadIdx.x;
    const int wid = tid >> 5;
    const int lid = tid & 31;

    if (wid == 0) TCGEN05_ALLOC(sb + SM_TMEMPTR, 256);
    if (tid == 0) {
#pragma unroll
        for (int s = 0; s < NSTG; s++) {
            MBARRIER_INIT(sb + SM_FULL + 8 * s, 256);  // one arrive per producer
            MBARRIER_INIT(sb + SM_DONE + 8 * s, 1);    // tcgen05.commit arrival
        }
    }
    __syncthreads();
    uint32_t tmem;
    asm volatile("ld.shared.b32 %0, [%1];" : "=r"(tmem) : "r"(sb + SM_TMEMPTR));

    const size_t m0 = (size_t)blockIdx.y * BM;
    const size_t n0 = (size_t)blockIdx.x * BN;

    // ---------------- producers: tids 0..255, 4 A + 8 B slots of 16B ----------
    if (tid < 256) {
        uint32_t a_soff[4], b_soff[8];
        size_t a_goff[4], b_goff[8];
#pragma unroll
        for (int i = 0; i < 4; i++) {
            int idx = tid + i * 256;
            int r = idx >> 3, c16 = idx & 7;
            a_soff[i] = SMEM_SWIZZLE_128B((uint32_t)(r * 128 + c16 * 16));
            a_goff[i] = (m0 + r) * (size_t)I_DIM + (size_t)c16 * 8;
        }
#pragma unroll
        for (int i = 0; i < 8; i++) {
            int idx = tid + i * 256;
            int r = idx >> 3, c16 = idx & 7;
            b_soff[i] = (uint32_t)A_BYTES + SMEM_SWIZZLE_128B((uint32_t)(r * 128 + c16 * 16));
            b_goff[i] = (n0 + r) * (size_t)I_DIM + (size_t)c16 * 8;
        }
#pragma unroll 1
        for (int c = 0; c < NCH; c++) {
            int s = c & (NSTG - 1);
            if (c >= NSTG)                                 // stage reuse gate
                MBARRIER_WAIT_PARITY(sb + SM_DONE + 8 * s, ((c >> 2) - 1) & 1);
            uint32_t base = sb + SM_TILES + s * STG_BYTES;
            size_t kk = (size_t)c * BK;
#pragma unroll
            for (int i = 0; i < 4; i++) cp_async16(base + a_soff[i], g_Ah + a_goff[i] + kk);
#pragma unroll
            for (int i = 0; i < 8; i++) cp_async16(base + b_soff[i], g_Bh + b_goff[i] + kk);
            CP_ASYNC_MBAR_ARRIVE(sb + SM_FULL + 8 * s);
        }
    }

    // ---------------- MMA issuer: warp 8, one elected lane ----------------
    if (wid == 8) {
        if (elect_one_pred()) {
#pragma unroll 1
            for (int k = 0; k < NCH; k++) {
                int s = k & (NSTG - 1);
                MBARRIER_WAIT_PARITY(sb + SM_FULL + 8 * s, (k >> 2) & 1);
                FENCE_PROXY_ASYNC_SHARED_CTA();
                uint32_t base = sb + SM_TILES + s * STG_BYTES;
                uint64_t ad = MAKE_SMEM_DESC(base);
                uint64_t bd = MAKE_SMEM_DESC(base + A_BYTES);
                bool first = (k == 0);
#pragma unroll
                for (int j = 0; j < 4; j++)   // 4 x K=16 cover BK=64 (+2 = 32B)
                    mma_f16_ss(tmem, ad + j * 2, bd + j * 2, IDESC, !(first && j == 0));
                TCGEN05_COMMIT(sb + SM_DONE + 8 * s);
            }
        }
    }

    // ---------------- epilogue: wait final chunk's MMA, drain TMEM ----------
    MBARRIER_WAIT_PARITY(sb + SM_DONE + 8 * ((NCH - 1) & (NSTG - 1)),
                         ((NCH - 1) >> 2) & 1);
    TCGEN05_FENCE_AFTER();

    if (wid < 4) {
        size_t row = m0 + (size_t)(wid * 32 + lid);
        float* op = out + row * (size_t)O_DIM + n0;
#pragma unroll 1
        for (int cb = 0; cb < 8; cb++) {
            uint32_t r[32];
            TCGEN05_LD_32X32B_X32(r, tmem + cb * 32);
            TCGEN05_WAIT_LD();
#pragma unroll
            for (int q = 0; q < 8; q++) {
                float4 v;
                v.x = __uint_as_float(r[q * 4 + 0]);
                v.y = __uint_as_float(r[q * 4 + 1]);
                v.z = __uint_as_float(r[q * 4 + 2]);
                v.w = __uint_as_float(r[q * 4 + 3]);
                *reinterpret_cast<float4*>(op + cb * 32 + q * 4) = v;
            }
        }
    }

    __syncthreads();
    if (wid == 0) {
        TCGEN05_RELINQUISH_ALLOC_PERMIT();
        TCGEN05_DEALLOC(tmem, 256);
    }
#endif  // TCG_OK
}

// ===========================================================================
// PATH B: portable mma.sync fallback (fp16) — empty body in the live cubin;
// launched only if the runtime-loaded tcgen05 kernel is the empty variant.
// ===========================================================================
constexpr int FBM = 128, FBN = 128, FBK = 64;
constexpr int FNCH = I_DIM / FBK;
constexpr int FSTG = 4;
constexpr int F_ABYTES = FBM * 128;
constexpr int F_STGB = F_ABYTES + FBN * 128;
constexpr int F_SMEM = FSTG * F_STGB;

__global__ void __launch_bounds__(256, 1)
nvfp4_gemm_mmasync(float* __restrict__ out) {
#if !TCG_OK
    extern __shared__ char smem[];
    const uint32_t sb = smem_to_u32(smem);
    const int tid = (int)threadIdx.x;
    const int wid = tid >> 5;
    const int lane = tid & 31;
    const int wm = wid & 1;
    const int wn = wid >> 1;

    const size_t m0 = (size_t)blockIdx.y * FBM;
    const size_t n0 = (size_t)blockIdx.x * FBN;

    uint32_t soff[8];
    size_t goff[8];
#pragma unroll
    for (int i = 0; i < 8; i++) {
        int idx = tid + i * 256;
        if (i < 4) {
            int r = idx >> 3, c16 = idx & 7;
            soff[i] = SMEM_SWIZZLE_128B((uint32_t)(r * 128 + c16 * 16));
            goff[i] = (m0 + r) * (size_t)I_DIM + (size_t)c16 * 8;
        } else {
            int idx2 = idx - 1024;
            int r = idx2 >> 3, c16 = idx2 & 7;
            soff[i] = (uint32_t)F_ABYTES + SMEM_SWIZZLE_128B((uint32_t)(r * 128 + c16 * 16));
            goff[i] = (n0 + r) * (size_t)I_DIM + (size_t)c16 * 8;
        }
    }

    auto load_chunk = [&](int c) {
        int s = c & (FSTG - 1);
        uint32_t base = sb + s * F_STGB;
        size_t kk = (size_t)c * FBK;
#pragma unroll
        for (int i = 0; i < 4; i++) cp_async16(base + soff[i], g_Ah + goff[i] + kk);
#pragma unroll
        for (int i = 4; i < 8; i++) cp_async16(base + soff[i], g_Bh + goff[i] + kk);
    };

    uint32_t arow128[4], axor[4];
    const uint32_t ahix = (uint32_t)((lane >> 4) * 16);
#pragma unroll
    for (int i = 0; i < 4; i++) {
        int row = wm * 64 + i * 16 + (lane & 7) + ((lane >> 3) & 1) * 8;
        arow128[i] = (uint32_t)(row * 128);
        axor[i] = (uint32_t)((row & 7) << 4);
    }
    uint32_t brow128[2], bxor[2];
    const uint32_t bhix = (uint32_t)(((lane >> 3) & 1) * 16);
#pragma unroll
    for (int jj = 0; jj < 2; jj++) {
        int row = wn * 32 + jj * 16 + (lane & 7) + ((lane >> 4) & 1) * 8;
        brow128[jj] = (uint32_t)(row * 128);
        bxor[jj] = (uint32_t)((row & 7) << 4);
    }

    float c[4][4][4];
#pragma unroll
    for (int i = 0; i < 4; i++)
#pragma unroll
        for (int j = 0; j < 4; j++)
#pragma unroll
            for (int r = 0; r < 4; r++) c[i][j][r] = 0.0f;

#pragma unroll 1
    for (int cch = 0; cch < FSTG; cch++) { load_chunk(cch); CP_COMMIT(); }

#pragma unroll 1
    for (int k = 0; k < FNCH; k++) {
        CP_WAIT_GROUP_3();
        __syncthreads();
        uint32_t Abase = sb + (uint32_t)((k & (FSTG - 1)) * F_STGB);
        uint32_t Bbase = Abase + F_ABYTES;
#pragma unroll
        for (int q = 0; q < 4; q++) {
            uint32_t qa = (uint32_t)(q * 32) + ahix;
            uint32_t qb = (uint32_t)(q * 32) + bhix;
            uint32_t a[4][4], b[2][4];
#pragma unroll
            for (int i = 0; i < 4; i++)
                ldsm_x4(a[i], Abase + arow128[i] + (qa ^ axor[i]));
#pragma unroll
            for (int jj = 0; jj < 2; jj++)
                ldsm_x4(b[jj], Bbase + brow128[jj] + (qb ^ bxor[jj]));
#pragma unroll
            for (int i = 0; i < 4; i++)
#pragma unroll
                for (int jj = 0; jj < 2; jj++) {
                    mma16816_f16(c[i][2 * jj + 0], a[i], &b[jj][0]);
                    mma16816_f16(c[i][2 * jj + 1], a[i], &b[jj][2]);
                }
        }
        __syncthreads();
        if (k + FSTG < FNCH) load_chunk(k + FSTG);
        CP_COMMIT();
    }

    const size_t rbase = m0 + (size_t)(wm * 64) + (size_t)(lane >> 2);
    const size_t cbase = n0 + (size_t)(wn * 32) + (size_t)((lane & 3) * 2);
#pragma unroll
    for (int i = 0; i < 4; i++)
#pragma unroll
        for (int j = 0; j < 4; j++) {
            size_t row = rbase + (size_t)(i * 16);
            size_t col = cbase + (size_t)(j * 8);
            *reinterpret_cast<float2*>(out + row * O_DIM + col) =
                make_float2(c[i][j][0], c[i][j][1]);
            *reinterpret_cast<float2*>(out + (row + 8) * O_DIM + col) =
                make_float2(c[i][j][2], c[i][j][3]);
        }
#endif  // !TCG_OK
}

// ---------------------------------------------------------------------------
// Launch
// ---------------------------------------------------------------------------
extern "C" void kernel_launch(void* const* d_in, const int* in_sizes, int n_in,
                              void* d_out, int out_size) {
    const float* x   = (const float*)d_in[0];
    const float* w   = (const float*)d_in[1];
    const float* pba = (const float*)d_in[2];
    const float* gam = (const float*)d_in[3];
    float* out = (float*)d_out;

    cudaFuncSetAttribute(nvfp4_gemm_tcgen05,
                         cudaFuncAttributeMaxDynamicSharedMemorySize, SMEM_DYN);
    cudaFuncSetAttribute(nvfp4_gemm_mmasync,
                         cudaFuncAttributeMaxDynamicSharedMemorySize, F_SMEM);

    // Which cubin did the runtime load? Real tcgen05 kernel uses many regs;
    // the empty-body variant (non-arch-specific pass) uses ~16.
    cudaFuncAttributes attr{};
    cudaFuncGetAttributes(&attr, nvfp4_gemm_tcgen05);
    const bool tcg_live = (attr.numRegs >= 32);

    {
        prep_kernel<<<(unsigned)((PREP_ITEMS + 255) / 256), 256>>>(x, w, pba, gam);
    }
    {
        dim3 grid(O_DIM / BN, T_DIM / BM, 1);   // (16, 64) = 1024 CTAs
        nvfp4_gemm_tcgen05<<<grid, GEMM_THREADS, SMEM_DYN>>>(out);
    }
    if (!tcg_live) {
        dim3 grid(O_DIM / FBN, T_DIM / FBM, 1); // insurance path
        nvfp4_gemm_mmasync<<<grid, 256, F_SMEM>>>(out);
    }
}